// round 5
// baseline (speedup 1.0000x reference)
#include <cuda_runtime.h>
#include <cuda_fp16.h>

#define NN 100000
#define NE 3200000
#define NG 1000
#define SCAN_BLK 1024
#define SCAN_NBLK ((NN + SCAN_BLK - 1) / SCAN_BLK)   // 98

// ---------------- scratch (device globals) ----------------
__device__ __align__(16) __half g_msg1[NN * 16];
__device__ __align__(16) float  g_root1[NN * 16];
__device__ __align__(16) __half g_msg2[NN * 32];
__device__ __align__(16) float  g_root2[NN * 32];
__device__ __align__(16) __half g_msg3[NN * 32];
__device__ __align__(16) float  g_root3[NN * 32];
__device__ __align__(16) float  g_pooled[NG * 32];
__device__ int g_cnt[NN];
__device__ int g_rowptr[NN + 1];
__device__ int g_wptr[NN];
__device__ int g_srcs[NE];
__device__ int g_bsum[SCAN_NBLK];
__device__ int g_ei64;
__device__ int g_b64;

// ---------------- helpers ----------------
__device__ __forceinline__ void red4(float* addr, float4 v) {
    asm volatile("red.global.add.v4.f32 [%0], {%1,%2,%3,%4};"
                 :: "l"(addr), "f"(v.x), "f"(v.y), "f"(v.z), "f"(v.w) : "memory");
}
__device__ __forceinline__ unsigned pk(float a, float b) {
    __half2 h = __floats2half2_rn(a, b);
    return reinterpret_cast<unsigned&>(h);
}
__device__ __forceinline__ void acc_h2x2(float4& acc, unsigned lo, unsigned hi) {
    __half2 h0 = reinterpret_cast<__half2&>(lo);
    __half2 h1 = reinterpret_cast<__half2&>(hi);
    float2 f0 = __half22float2(h0), f1 = __half22float2(h1);
    acc.x += f0.x; acc.y += f0.y; acc.z += f1.x; acc.w += f1.y;
}

// Detect int64 vs int32 for edge_index / batch (JAX x64 ambiguity).
__global__ void k_detect(const int* __restrict__ ei, const int* __restrict__ batch) {
    if (threadIdx.x != 0) return;
    int all0 = 1;
    for (int j = 0; j < 64; j++) {
        long long p = 1 + 2LL * j * 49999;
        if (ei[p] != 0) { all0 = 0; break; }
    }
    g_ei64 = all0;
    int all0b = 1;
    for (int j = 0; j < 32; j++) {
        int p = (NN - 1) - 2 * j;
        if (batch[p] != 0) { all0b = 0; break; }
    }
    g_b64 = all0b;
}

__global__ void k_zero() {
    int i = blockIdx.x * 256 + threadIdx.x;
    if (i < NN) g_cnt[i] = 0;
    if (i < NG * 32) g_pooled[i] = 0.f;
}

// ---------------- CSR build ----------------
// 4 edges per thread, vectorized dst loads.
__global__ __launch_bounds__(256) void k_hist(const void* __restrict__ ei) {
    int t = blockIdx.x * 256 + threadIdx.x;
    int e = t * 4;
    if (e >= NE) return;
    if (g_ei64) {
        const longlong2* p = (const longlong2*)((const long long*)ei + NE);
        longlong2 a = p[t * 2], b = p[t * 2 + 1];
        atomicAdd(&g_cnt[(int)a.x], 1);
        atomicAdd(&g_cnt[(int)a.y], 1);
        atomicAdd(&g_cnt[(int)b.x], 1);
        atomicAdd(&g_cnt[(int)b.y], 1);
    } else {
        const int4* p = (const int4*)((const int*)ei + NE);
        int4 a = p[t];
        atomicAdd(&g_cnt[a.x], 1);
        atomicAdd(&g_cnt[a.y], 1);
        atomicAdd(&g_cnt[a.z], 1);
        atomicAdd(&g_cnt[a.w], 1);
    }
}

// Pass 1: per-block exclusive scan of g_cnt into g_rowptr; block totals to g_bsum.
__global__ __launch_bounds__(SCAN_BLK) void k_scan1() {
    __shared__ int warpsum[32];
    int tid = threadIdx.x;
    int i = blockIdx.x * SCAN_BLK + tid;
    int val = (i < NN) ? g_cnt[i] : 0;
    int lane = tid & 31, wid = tid >> 5;
    int inc = val;
#pragma unroll
    for (int off = 1; off < 32; off <<= 1) {
        int v = __shfl_up_sync(0xffffffffu, inc, off);
        if (lane >= off) inc += v;
    }
    if (lane == 31) warpsum[wid] = inc;
    __syncthreads();
    if (wid == 0) {
        int ws = warpsum[lane];
#pragma unroll
        for (int off = 1; off < 32; off <<= 1) {
            int v = __shfl_up_sync(0xffffffffu, ws, off);
            if (lane >= off) ws += v;
        }
        warpsum[lane] = ws;
    }
    __syncthreads();
    int wofs = (wid == 0) ? 0 : warpsum[wid - 1];
    int excl = wofs + inc - val;
    if (i < NN) g_rowptr[i] = excl;
    if (tid == SCAN_BLK - 1) g_bsum[blockIdx.x] = wofs + inc;
}

// Pass 2: exclusive-scan the 98 block sums (one block).
__global__ __launch_bounds__(128) void k_scan2() {
    __shared__ int s[128];
    int tid = threadIdx.x;
    int val = (tid < SCAN_NBLK) ? g_bsum[tid] : 0;
    s[tid] = val;
    __syncthreads();
#pragma unroll
    for (int off = 1; off < 128; off <<= 1) {
        int v = (tid >= off) ? s[tid - off] : 0;
        __syncthreads();
        s[tid] += v;
        __syncthreads();
    }
    if (tid < SCAN_NBLK) g_bsum[tid] = s[tid] - val;
}

// Pass 3: add block offsets; mirror into wptr; set rowptr[NN].
__global__ __launch_bounds__(SCAN_BLK) void k_scan3() {
    int i = blockIdx.x * SCAN_BLK + threadIdx.x;
    if (i == 0) g_rowptr[NN] = NE;
    if (i >= NN) return;
    int r = g_rowptr[i] + g_bsum[blockIdx.x];
    g_rowptr[i] = r;
    g_wptr[i] = r;
}

// 2 edges per thread.
__global__ __launch_bounds__(256) void k_scatter(const void* __restrict__ ei) {
    int t = blockIdx.x * 256 + threadIdx.x;
    int e = t * 2;
    if (e >= NE) return;
    int s0, s1, d0, d1;
    if (g_ei64) {
        const longlong2* ps = (const longlong2*)ei;
        longlong2 sv = ps[t];
        longlong2 dv = ps[NE / 2 + t];
        s0 = (int)sv.x; s1 = (int)sv.y; d0 = (int)dv.x; d1 = (int)dv.y;
    } else {
        const int2* ps = (const int2*)ei;
        int2 sv = ps[t];
        int2 dv = ps[NE / 2 + t];
        s0 = sv.x; s1 = sv.y; d0 = dv.x; d1 = dv.y;
    }
    int p0 = atomicAdd(&g_wptr[d0], 1);
    g_srcs[p0] = s0;
    int p1 = atomicAdd(&g_wptr[d1], 1);
    g_srcs[p1] = s1;
}

// ---------------- layer 1 node matmuls: msg1 = x@W1n (fp16), root1 = x@W1r ----
__global__ __launch_bounds__(256) void k_lin1(const float* __restrict__ x,
                                              const float* __restrict__ W1r,
                                              const float* __restrict__ W1n) {
    __shared__ float4 sWn[512];  // 128x16
    __shared__ float4 sWr[512];
    int tid = threadIdx.x;
    for (int i = tid; i < 512; i += 256) {
        sWn[i] = ((const float4*)W1n)[i];
        sWr[i] = ((const float4*)W1r)[i];
    }
    __syncthreads();
    int n = blockIdx.x * 256 + tid;
    if (n >= NN) return;
    float accn[16], accr[16];
#pragma unroll
    for (int o = 0; o < 16; o++) { accn[o] = 0.f; accr[o] = 0.f; }
    const float4* xr = (const float4*)(x + (long long)n * 128);
#pragma unroll 4
    for (int k4 = 0; k4 < 32; k4++) {
        float4 xv = xr[k4];
        float xs[4] = {xv.x, xv.y, xv.z, xv.w};
#pragma unroll
        for (int kk = 0; kk < 4; kk++) {
            int k = (k4 << 2) + kk;
#pragma unroll
            for (int o4 = 0; o4 < 4; o4++) {
                float4 wn = sWn[(k << 2) + o4];
                float4 wr = sWr[(k << 2) + o4];
                accn[(o4 << 2) + 0] += xs[kk] * wn.x;
                accn[(o4 << 2) + 1] += xs[kk] * wn.y;
                accn[(o4 << 2) + 2] += xs[kk] * wn.z;
                accn[(o4 << 2) + 3] += xs[kk] * wn.w;
                accr[(o4 << 2) + 0] += xs[kk] * wr.x;
                accr[(o4 << 2) + 1] += xs[kk] * wr.y;
                accr[(o4 << 2) + 2] += xs[kk] * wr.z;
                accr[(o4 << 2) + 3] += xs[kk] * wr.w;
            }
        }
    }
    uint4 m0, m1;
    m0.x = pk(accn[0], accn[1]);   m0.y = pk(accn[2], accn[3]);
    m0.z = pk(accn[4], accn[5]);   m0.w = pk(accn[6], accn[7]);
    m1.x = pk(accn[8], accn[9]);   m1.y = pk(accn[10], accn[11]);
    m1.z = pk(accn[12], accn[13]); m1.w = pk(accn[14], accn[15]);
    uint4* mp = (uint4*)(g_msg1 + n * 16);
    mp[0] = m0; mp[1] = m1;
    float4* r = (float4*)(g_root1 + n * 16);
#pragma unroll
    for (int o4 = 0; o4 < 4; o4++)
        r[o4] = make_float4(accr[o4 * 4], accr[o4 * 4 + 1], accr[o4 * 4 + 2], accr[o4 * 4 + 3]);
}

// ====== FUSED gather1 + node2, 4 lanes/node ======
// Lane q handles h1 channels {4q..4q+3} (one 8B msg1 load per edge), then the
// group exchanges h1 via width-4 shuffles; lane emits msg2/root2 channels
// {8q..8q+7}. n clamped so warps stay full for shuffles (duplicate groups
// write identical values — benign).
__global__ __launch_bounds__(256) void k_g1n2(const float* __restrict__ b1,
                                              const float* __restrict__ W2r,
                                              const float* __restrict__ W2n) {
    __shared__ float4 sWn[128];  // 16x32
    __shared__ float4 sWr[128];
    __shared__ float sb1[16];
    int tid = threadIdx.x;
    if (tid < 128) { sWn[tid] = ((const float4*)W2n)[tid]; sWr[tid] = ((const float4*)W2r)[tid]; }
    if (tid < 16) sb1[tid] = b1[tid];
    __syncthreads();
    int t = blockIdx.x * 256 + tid;
    int n = t >> 2;
    if (n >= NN) n = NN - 1;
    int q = t & 3;
    int beg = g_rowptr[n], end = g_rowptr[n + 1];
    float4 acc = make_float4(0.f, 0.f, 0.f, 0.f);
    const uint2* mp = (const uint2*)g_msg1;  // row = 4 uint2 (16 half)
#pragma unroll 4
    for (int e = beg; e < end; e++) {
        int s = __ldg(&g_srcs[e]);
        uint2 v = mp[s * 4 + q];
        acc_h2x2(acc, v.x, v.y);
    }
    __syncwarp();
    float4 r = ((const float4*)g_root1)[n * 4 + q];
    float h[4];
    h[0] = fmaxf(r.x + acc.x + sb1[4 * q + 0], 0.f);
    h[1] = fmaxf(r.y + acc.y + sb1[4 * q + 1], 0.f);
    h[2] = fmaxf(r.z + acc.z + sb1[4 * q + 2], 0.f);
    h[3] = fmaxf(r.w + acc.w + sb1[4 * q + 3], 0.f);
    // matmul: lane outputs channels 8q..8q+7
    float4 am0 = make_float4(0.f, 0.f, 0.f, 0.f), am1 = am0;
    float4 ar0 = am0, ar1 = am0;
#pragma unroll
    for (int kk = 0; kk < 4; kk++) {
#pragma unroll
        for (int c = 0; c < 4; c++) {
            float hk = __shfl_sync(0xffffffffu, h[c], kk, 4);  // k = kk*4+c
            int k = kk * 4 + c;
            float4 wn0 = sWn[k * 8 + 2 * q], wn1 = sWn[k * 8 + 2 * q + 1];
            float4 wr0 = sWr[k * 8 + 2 * q], wr1 = sWr[k * 8 + 2 * q + 1];
            am0.x += hk * wn0.x; am0.y += hk * wn0.y; am0.z += hk * wn0.z; am0.w += hk * wn0.w;
            am1.x += hk * wn1.x; am1.y += hk * wn1.y; am1.z += hk * wn1.z; am1.w += hk * wn1.w;
            ar0.x += hk * wr0.x; ar0.y += hk * wr0.y; ar0.z += hk * wr0.z; ar0.w += hk * wr0.w;
            ar1.x += hk * wr1.x; ar1.y += hk * wr1.y; ar1.z += hk * wr1.z; ar1.w += hk * wr1.w;
        }
    }
    uint4 m;
    m.x = pk(am0.x, am0.y); m.y = pk(am0.z, am0.w);
    m.z = pk(am1.x, am1.y); m.w = pk(am1.z, am1.w);
    ((uint4*)g_msg2)[n * 4 + q] = m;
    ((float4*)g_root2)[n * 8 + 2 * q]     = ar0;
    ((float4*)g_root2)[n * 8 + 2 * q + 1] = ar1;
}

// ====== FUSED gather2 + node3, 4 lanes/node ======
// Lane q handles h2 channels {8q..8q+7} (one 16B msg2 load per edge), exchanges
// via width-4 shuffles, emits msg3/root3 channels {8q..8q+7}.
__global__ __launch_bounds__(256) void k_g2n3(const float* __restrict__ b2,
                                              const float* __restrict__ W3r,
                                              const float* __restrict__ W3n) {
    __shared__ float4 sWn[256];  // 32x32
    __shared__ float4 sWr[256];
    __shared__ float sb2[32];
    int tid = threadIdx.x;
    if (tid < 256) { sWn[tid] = ((const float4*)W3n)[tid]; sWr[tid] = ((const float4*)W3r)[tid]; }
    if (tid < 32) sb2[tid] = b2[tid];
    __syncthreads();
    int t = blockIdx.x * 256 + tid;
    int n = t >> 2;
    if (n >= NN) n = NN - 1;
    int q = t & 3;
    int beg = g_rowptr[n], end = g_rowptr[n + 1];
    float4 acc0 = make_float4(0.f, 0.f, 0.f, 0.f), acc1 = acc0;
    const uint4* mp = (const uint4*)g_msg2;  // row = 4 uint4 (32 half)
#pragma unroll 4
    for (int e = beg; e < end; e++) {
        int s = __ldg(&g_srcs[e]);
        uint4 v = mp[s * 4 + q];
        acc_h2x2(acc0, v.x, v.y);
        acc_h2x2(acc1, v.z, v.w);
    }
    __syncwarp();
    float4 r0 = ((const float4*)g_root2)[n * 8 + 2 * q];
    float4 r1 = ((const float4*)g_root2)[n * 8 + 2 * q + 1];
    float h[8];
    h[0] = fmaxf(r0.x + acc0.x + sb2[8 * q + 0], 0.f);
    h[1] = fmaxf(r0.y + acc0.y + sb2[8 * q + 1], 0.f);
    h[2] = fmaxf(r0.z + acc0.z + sb2[8 * q + 2], 0.f);
    h[3] = fmaxf(r0.w + acc0.w + sb2[8 * q + 3], 0.f);
    h[4] = fmaxf(r1.x + acc1.x + sb2[8 * q + 4], 0.f);
    h[5] = fmaxf(r1.y + acc1.y + sb2[8 * q + 5], 0.f);
    h[6] = fmaxf(r1.z + acc1.z + sb2[8 * q + 6], 0.f);
    h[7] = fmaxf(r1.w + acc1.w + sb2[8 * q + 7], 0.f);
    float4 am0 = make_float4(0.f, 0.f, 0.f, 0.f), am1 = am0;
    float4 ar0 = am0, ar1 = am0;
#pragma unroll
    for (int kk = 0; kk < 4; kk++) {
#pragma unroll
        for (int c = 0; c < 8; c++) {
            float hk = __shfl_sync(0xffffffffu, h[c], kk, 4);  // k = kk*8+c
            int k = kk * 8 + c;
            float4 wn0 = sWn[k * 8 + 2 * q], wn1 = sWn[k * 8 + 2 * q + 1];
            float4 wr0 = sWr[k * 8 + 2 * q], wr1 = sWr[k * 8 + 2 * q + 1];
            am0.x += hk * wn0.x; am0.y += hk * wn0.y; am0.z += hk * wn0.z; am0.w += hk * wn0.w;
            am1.x += hk * wn1.x; am1.y += hk * wn1.y; am1.z += hk * wn1.z; am1.w += hk * wn1.w;
            ar0.x += hk * wr0.x; ar0.y += hk * wr0.y; ar0.z += hk * wr0.z; ar0.w += hk * wr0.w;
            ar1.x += hk * wr1.x; ar1.y += hk * wr1.y; ar1.z += hk * wr1.z; ar1.w += hk * wr1.w;
        }
    }
    uint4 m;
    m.x = pk(am0.x, am0.y); m.y = pk(am0.z, am0.w);
    m.z = pk(am1.x, am1.y); m.w = pk(am1.z, am1.w);
    ((uint4*)g_msg3)[n * 4 + q] = m;
    ((float4*)g_root3)[n * 8 + 2 * q]     = ar0;
    ((float4*)g_root3)[n * 8 + 2 * q + 1] = ar1;
}

// -------- gather layer3 fused with pool, 4 lanes/node --------
__global__ __launch_bounds__(256) void k_gather3(const float* __restrict__ b3,
                                                 const void* __restrict__ batch) {
    int t = blockIdx.x * 256 + threadIdx.x;
    int n = t >> 2, q = t & 3;
    if (n >= NN) return;
    int beg = g_rowptr[n], end = g_rowptr[n + 1];
    float4 acc0 = make_float4(0.f, 0.f, 0.f, 0.f), acc1 = acc0;
    const uint4* mp = (const uint4*)g_msg3;
#pragma unroll 4
    for (int e = beg; e < end; e++) {
        int s = __ldg(&g_srcs[e]);
        uint4 v = mp[s * 4 + q];
        acc_h2x2(acc0, v.x, v.y);
        acc_h2x2(acc1, v.z, v.w);
    }
    float4 r0 = ((const float4*)g_root3)[n * 8 + 2 * q];
    float4 r1 = ((const float4*)g_root3)[n * 8 + 2 * q + 1];
    float4 h0, h1;
    h0.x = fmaxf(r0.x + acc0.x + b3[8 * q + 0], 0.f);
    h0.y = fmaxf(r0.y + acc0.y + b3[8 * q + 1], 0.f);
    h0.z = fmaxf(r0.z + acc0.z + b3[8 * q + 2], 0.f);
    h0.w = fmaxf(r0.w + acc0.w + b3[8 * q + 3], 0.f);
    h1.x = fmaxf(r1.x + acc1.x + b3[8 * q + 4], 0.f);
    h1.y = fmaxf(r1.y + acc1.y + b3[8 * q + 5], 0.f);
    h1.z = fmaxf(r1.z + acc1.z + b3[8 * q + 6], 0.f);
    h1.w = fmaxf(r1.w + acc1.w + b3[8 * q + 7], 0.f);
    int g;
    if (g_b64) g = (int)((const long long*)batch)[n];
    else       g = ((const int*)batch)[n];
    red4(g_pooled + g * 32 + 8 * q, h0);
    red4(g_pooled + g * 32 + 8 * q + 4, h1);
}

// ---------------- out = pooled @ Wlin + blin ----------------
__global__ __launch_bounds__(64) void k_final(const float* __restrict__ Wlin,
                                              const float* __restrict__ blin,
                                              float* __restrict__ out) {
    __shared__ float sW[32 * 64];
    int tid = threadIdx.x;
    for (int i = tid; i < 2048; i += 64) sW[i] = Wlin[i];
    __syncthreads();
    int g = blockIdx.x;
    float acc = blin[tid];
    const float* p = g_pooled + g * 32;
#pragma unroll
    for (int k = 0; k < 32; k++) acc += p[k] * sW[k * 64 + tid];
    out[g * 64 + tid] = acc;
}

// ---------------- launch ----------------
extern "C" void kernel_launch(void* const* d_in, const int* in_sizes, int n_in,
                              void* d_out, int out_size) {
    const float* x     = (const float*)d_in[0];
    const void*  ei    = d_in[1];
    const void*  batch = d_in[2];
    const float* W1r = (const float*)d_in[3];
    const float* W1n = (const float*)d_in[4];
    const float* b1  = (const float*)d_in[5];
    const float* W2r = (const float*)d_in[6];
    const float* W2n = (const float*)d_in[7];
    const float* b2  = (const float*)d_in[8];
    const float* W3r = (const float*)d_in[9];
    const float* W3n = (const float*)d_in[10];
    const float* b3  = (const float*)d_in[11];
    const float* Wlin = (const float*)d_in[12];
    const float* blin = (const float*)d_in[13];
    float* out = (float*)d_out;

    const int NODE_BLKS = (NN + 255) / 256;       // 391
    const int GATH_BLKS = (NN * 4 + 255) / 256;   // 1563

    k_detect<<<1, 1>>>((const int*)ei, (const int*)batch);
    k_zero<<<NODE_BLKS, 256>>>();
    k_hist<<<(NE / 4 + 255) / 256, 256>>>(ei);
    k_scan1<<<SCAN_NBLK, SCAN_BLK>>>();
    k_scan2<<<1, 128>>>();
    k_scan3<<<SCAN_NBLK, SCAN_BLK>>>();
    k_scatter<<<(NE / 2 + 255) / 256, 256>>>(ei);
    k_lin1<<<NODE_BLKS, 256>>>(x, W1r, W1n);
    k_g1n2<<<GATH_BLKS, 256>>>(b1, W2r, W2n);
    k_g2n3<<<GATH_BLKS, 256>>>(b2, W3r, W3n);
    k_gather3<<<GATH_BLKS, 256>>>(b3, batch);
    k_final<<<NG, 64>>>(Wlin, blin, out);
}

// round 6
// speedup vs baseline: 1.0254x; 1.0254x over previous
#include <cuda_runtime.h>
#include <cuda_fp16.h>

#define NN 100000
#define NE 3200000
#define NG 1000
#define SCAN_BLK 1024
#define SCAN_NBLK ((NN + SCAN_BLK - 1) / SCAN_BLK)   // 98

// ---------------- scratch (device globals) ----------------
__device__ __align__(16) __half g_msg1[NN * 16];
__device__ __align__(16) float  g_root1[NN * 16];
__device__ __align__(16) __half g_msg2[NN * 32];
__device__ __align__(16) float  g_root2[NN * 32];
__device__ __align__(16) __half g_msg3[NN * 32];
__device__ __align__(16) float  g_root3[NN * 32];
__device__ __align__(16) float  g_pooled[NG * 32];
__device__ int g_cnt[NN];
__device__ int g_rowptr[NN + 1];
__device__ int g_wptr[NN];
__device__ int g_srcs[NE];
__device__ int g_bsum[SCAN_NBLK];
__device__ int g_ei64;
__device__ int g_b64;

// ---------------- helpers ----------------
__device__ __forceinline__ void red4(float* addr, float4 v) {
    asm volatile("red.global.add.v4.f32 [%0], {%1,%2,%3,%4};"
                 :: "l"(addr), "f"(v.x), "f"(v.y), "f"(v.z), "f"(v.w) : "memory");
}
__device__ __forceinline__ unsigned pk(float a, float b) {
    __half2 h = __floats2half2_rn(a, b);
    return reinterpret_cast<unsigned&>(h);
}

// ---------------- init: zero buffers + parallel dtype detection ----------------
// For int64 data (values < 2^31, nonneg), odd int32 words are zero high halves.
__global__ void k_init(const int* __restrict__ ei, const int* __restrict__ batch) {
    int i = blockIdx.x * 256 + threadIdx.x;
    if (i < NN) g_cnt[i] = 0;
    if (i < NG * 32) g_pooled[i] = 0.f;
    if (blockIdx.x == 0) {
        __shared__ int s_ei, s_b;
        if (threadIdx.x == 0) { s_ei = 0; s_b = 0; }
        __syncthreads();
        if (threadIdx.x < 64) {
            long long p = 1 + 2LL * threadIdx.x * 49999;   // odd, < 6.4M
            if (ei[p] != 0) atomicOr(&s_ei, 1);
        } else if (threadIdx.x < 96) {
            int j = threadIdx.x - 64;
            int p = (NN - 1) - 2 * j;                      // odd, near top (sorted batch)
            if (batch[p] != 0) atomicOr(&s_b, 1);
        }
        __syncthreads();
        if (threadIdx.x == 0) { g_ei64 = (s_ei == 0); g_b64 = (s_b == 0); }
    }
}

// ---------------- CSR build ----------------
// 4 edges per thread, vectorized dst loads.
__global__ __launch_bounds__(256) void k_hist(const void* __restrict__ ei) {
    int t = blockIdx.x * 256 + threadIdx.x;
    int e = t * 4;
    if (e >= NE) return;
    if (g_ei64) {
        const longlong2* p = (const longlong2*)((const long long*)ei + NE);
        longlong2 a = p[t * 2], b = p[t * 2 + 1];
        atomicAdd(&g_cnt[(int)a.x], 1);
        atomicAdd(&g_cnt[(int)a.y], 1);
        atomicAdd(&g_cnt[(int)b.x], 1);
        atomicAdd(&g_cnt[(int)b.y], 1);
    } else {
        const int4* p = (const int4*)((const int*)ei + NE);
        int4 a = p[t];
        atomicAdd(&g_cnt[a.x], 1);
        atomicAdd(&g_cnt[a.y], 1);
        atomicAdd(&g_cnt[a.z], 1);
        atomicAdd(&g_cnt[a.w], 1);
    }
}

// Pass 1: per-block exclusive scan of g_cnt into g_rowptr; block totals to g_bsum.
__global__ __launch_bounds__(SCAN_BLK) void k_scan1() {
    __shared__ int warpsum[32];
    int tid = threadIdx.x;
    int i = blockIdx.x * SCAN_BLK + tid;
    int val = (i < NN) ? g_cnt[i] : 0;
    int lane = tid & 31, wid = tid >> 5;
    int inc = val;
#pragma unroll
    for (int off = 1; off < 32; off <<= 1) {
        int v = __shfl_up_sync(0xffffffffu, inc, off);
        if (lane >= off) inc += v;
    }
    if (lane == 31) warpsum[wid] = inc;
    __syncthreads();
    if (wid == 0) {
        int ws = warpsum[lane];
#pragma unroll
        for (int off = 1; off < 32; off <<= 1) {
            int v = __shfl_up_sync(0xffffffffu, ws, off);
            if (lane >= off) ws += v;
        }
        warpsum[lane] = ws;
    }
    __syncthreads();
    int wofs = (wid == 0) ? 0 : warpsum[wid - 1];
    int excl = wofs + inc - val;
    if (i < NN) g_rowptr[i] = excl;
    if (tid == SCAN_BLK - 1) g_bsum[blockIdx.x] = wofs + inc;
}

// Pass 2: exclusive-scan the 98 block sums (one block).
__global__ __launch_bounds__(128) void k_scan2() {
    __shared__ int s[128];
    int tid = threadIdx.x;
    int val = (tid < SCAN_NBLK) ? g_bsum[tid] : 0;
    s[tid] = val;
    __syncthreads();
#pragma unroll
    for (int off = 1; off < 128; off <<= 1) {
        int v = (tid >= off) ? s[tid - off] : 0;
        __syncthreads();
        s[tid] += v;
        __syncthreads();
    }
    if (tid < SCAN_NBLK) g_bsum[tid] = s[tid] - val;
}

// Pass 3: add block offsets; mirror into wptr; set rowptr[NN].
__global__ __launch_bounds__(SCAN_BLK) void k_scan3() {
    int i = blockIdx.x * SCAN_BLK + threadIdx.x;
    if (i == 0) g_rowptr[NN] = NE;
    if (i >= NN) return;
    int r = g_rowptr[i] + g_bsum[blockIdx.x];
    g_rowptr[i] = r;
    g_wptr[i] = r;
}

// 2 edges per thread.
__global__ __launch_bounds__(256) void k_scatter(const void* __restrict__ ei) {
    int t = blockIdx.x * 256 + threadIdx.x;
    int e = t * 2;
    if (e >= NE) return;
    int s0, s1, d0, d1;
    if (g_ei64) {
        const longlong2* ps = (const longlong2*)ei;
        longlong2 sv = ps[t];
        longlong2 dv = ps[NE / 2 + t];
        s0 = (int)sv.x; s1 = (int)sv.y; d0 = (int)dv.x; d1 = (int)dv.y;
    } else {
        const int2* ps = (const int2*)ei;
        int2 sv = ps[t];
        int2 dv = ps[NE / 2 + t];
        s0 = sv.x; s1 = sv.y; d0 = dv.x; d1 = dv.y;
    }
    int p0 = atomicAdd(&g_wptr[d0], 1);
    g_srcs[p0] = s0;
    int p1 = atomicAdd(&g_wptr[d1], 1);
    g_srcs[p1] = s1;
}

// ---------------- layer 1 node matmuls: msg1 = x@W1n (fp16), root1 = x@W1r ----
__global__ __launch_bounds__(256) void k_lin1(const float* __restrict__ x,
                                              const float* __restrict__ W1r,
                                              const float* __restrict__ W1n) {
    __shared__ float4 sWn[512];  // 128x16
    __shared__ float4 sWr[512];
    int tid = threadIdx.x;
    for (int i = tid; i < 512; i += 256) {
        sWn[i] = ((const float4*)W1n)[i];
        sWr[i] = ((const float4*)W1r)[i];
    }
    __syncthreads();
    int n = blockIdx.x * 256 + tid;
    if (n >= NN) return;
    float accn[16], accr[16];
#pragma unroll
    for (int o = 0; o < 16; o++) { accn[o] = 0.f; accr[o] = 0.f; }
    const float4* xr = (const float4*)(x + (long long)n * 128);
#pragma unroll 4
    for (int k4 = 0; k4 < 32; k4++) {
        float4 xv = xr[k4];
        float xs[4] = {xv.x, xv.y, xv.z, xv.w};
#pragma unroll
        for (int kk = 0; kk < 4; kk++) {
            int k = (k4 << 2) + kk;
#pragma unroll
            for (int o4 = 0; o4 < 4; o4++) {
                float4 wn = sWn[(k << 2) + o4];
                float4 wr = sWr[(k << 2) + o4];
                accn[(o4 << 2) + 0] += xs[kk] * wn.x;
                accn[(o4 << 2) + 1] += xs[kk] * wn.y;
                accn[(o4 << 2) + 2] += xs[kk] * wn.z;
                accn[(o4 << 2) + 3] += xs[kk] * wn.w;
                accr[(o4 << 2) + 0] += xs[kk] * wr.x;
                accr[(o4 << 2) + 1] += xs[kk] * wr.y;
                accr[(o4 << 2) + 2] += xs[kk] * wr.z;
                accr[(o4 << 2) + 3] += xs[kk] * wr.w;
            }
        }
    }
    uint4 m0, m1;
    m0.x = pk(accn[0], accn[1]);   m0.y = pk(accn[2], accn[3]);
    m0.z = pk(accn[4], accn[5]);   m0.w = pk(accn[6], accn[7]);
    m1.x = pk(accn[8], accn[9]);   m1.y = pk(accn[10], accn[11]);
    m1.z = pk(accn[12], accn[13]); m1.w = pk(accn[14], accn[15]);
    uint4* mp = (uint4*)(g_msg1 + n * 16);
    mp[0] = m0; mp[1] = m1;
    float4* r = (float4*)(g_root1 + n * 16);
#pragma unroll
    for (int o4 = 0; o4 < 4; o4++)
        r[o4] = make_float4(accr[o4 * 4], accr[o4 * 4 + 1], accr[o4 * 4 + 2], accr[o4 * 4 + 3]);
}

// ====== FUSED gather1 + node2, 8 lanes/node ======
__global__ __launch_bounds__(256) void k_g1n2(const float* __restrict__ b1,
                                              const float* __restrict__ W2r,
                                              const float* __restrict__ W2n) {
    __shared__ float4 sWn[128];  // 16x32
    __shared__ float4 sWr[128];
    __shared__ float sb1[16];
    int tid = threadIdx.x;
    if (tid < 128) { sWn[tid] = ((const float4*)W2n)[tid]; sWr[tid] = ((const float4*)W2r)[tid]; }
    if (tid < 16) sb1[tid] = b1[tid];
    __syncthreads();
    int t = blockIdx.x * 256 + tid;
    int n = t >> 3, q = t & 7;
    int beg = g_rowptr[n], end = g_rowptr[n + 1];
    float accx = 0.f, accy = 0.f;
    const __half2* mp = (const __half2*)g_msg1;
#pragma unroll 4
    for (int e = beg; e < end; e++) {
        int s = __ldg(&g_srcs[e]);
        float2 f = __half22float2(mp[s * 8 + q]);
        accx += f.x; accy += f.y;
    }
    __syncwarp();
    float2 r = ((const float2*)g_root1)[n * 8 + q];
    float hx = fmaxf(r.x + accx + sb1[2 * q], 0.f);
    float hy = fmaxf(r.y + accy + sb1[2 * q + 1], 0.f);
    float4 am = make_float4(0.f, 0.f, 0.f, 0.f);
    float4 ar = make_float4(0.f, 0.f, 0.f, 0.f);
#pragma unroll
    for (int kk = 0; kk < 8; kk++) {
        float h0 = __shfl_sync(0xffffffffu, hx, kk, 8);
        float h1 = __shfl_sync(0xffffffffu, hy, kk, 8);
        float4 wn0 = sWn[(2 * kk) * 8 + q];
        float4 wr0 = sWr[(2 * kk) * 8 + q];
        float4 wn1 = sWn[(2 * kk + 1) * 8 + q];
        float4 wr1 = sWr[(2 * kk + 1) * 8 + q];
        am.x += h0 * wn0.x + h1 * wn1.x;  am.y += h0 * wn0.y + h1 * wn1.y;
        am.z += h0 * wn0.z + h1 * wn1.z;  am.w += h0 * wn0.w + h1 * wn1.w;
        ar.x += h0 * wr0.x + h1 * wr1.x;  ar.y += h0 * wr0.y + h1 * wr1.y;
        ar.z += h0 * wr0.z + h1 * wr1.z;  ar.w += h0 * wr0.w + h1 * wr1.w;
    }
    uint2 m;
    m.x = pk(am.x, am.y);
    m.y = pk(am.z, am.w);
    ((uint2*)g_msg2)[n * 8 + q] = m;
    ((float4*)g_root2)[n * 8 + q] = ar;
}

// ====== FUSED gather2 + node3, 8 lanes/node ======
__global__ __launch_bounds__(256) void k_g2n3(const float* __restrict__ b2,
                                              const float* __restrict__ W3r,
                                              const float* __restrict__ W3n) {
    __shared__ float4 sWn[256];  // 32x32
    __shared__ float4 sWr[256];
    __shared__ float sb2[32];
    int tid = threadIdx.x;
    if (tid < 256) { sWn[tid] = ((const float4*)W3n)[tid]; sWr[tid] = ((const float4*)W3r)[tid]; }
    if (tid < 32) sb2[tid] = b2[tid];
    __syncthreads();
    int t = blockIdx.x * 256 + tid;
    int n = t >> 3, q = t & 7;
    int beg = g_rowptr[n], end = g_rowptr[n + 1];
    float4 acc = make_float4(0.f, 0.f, 0.f, 0.f);
    const uint2* mp = (const uint2*)g_msg2;
#pragma unroll 4
    for (int e = beg; e < end; e++) {
        int s = __ldg(&g_srcs[e]);
        uint2 v = mp[s * 8 + q];
        __half2 h0 = reinterpret_cast<__half2&>(v.x);
        __half2 h1 = reinterpret_cast<__half2&>(v.y);
        float2 f0 = __half22float2(h0), f1 = __half22float2(h1);
        acc.x += f0.x; acc.y += f0.y; acc.z += f1.x; acc.w += f1.y;
    }
    __syncwarp();
    float4 r = ((const float4*)g_root2)[n * 8 + q];
    float h[4];
    h[0] = fmaxf(r.x + acc.x + sb2[4 * q + 0], 0.f);
    h[1] = fmaxf(r.y + acc.y + sb2[4 * q + 1], 0.f);
    h[2] = fmaxf(r.z + acc.z + sb2[4 * q + 2], 0.f);
    h[3] = fmaxf(r.w + acc.w + sb2[4 * q + 3], 0.f);
    float4 am = make_float4(0.f, 0.f, 0.f, 0.f);
    float4 ar = make_float4(0.f, 0.f, 0.f, 0.f);
#pragma unroll
    for (int kk = 0; kk < 8; kk++) {
#pragma unroll
        for (int c = 0; c < 4; c++) {
            float hk = __shfl_sync(0xffffffffu, h[c], kk, 8);
            int k = kk * 4 + c;
            float4 wn = sWn[k * 8 + q];
            float4 wr = sWr[k * 8 + q];
            am.x += hk * wn.x; am.y += hk * wn.y; am.z += hk * wn.z; am.w += hk * wn.w;
            ar.x += hk * wr.x; ar.y += hk * wr.y; ar.z += hk * wr.z; ar.w += hk * wr.w;
        }
    }
    uint2 m;
    m.x = pk(am.x, am.y);
    m.y = pk(am.z, am.w);
    ((uint2*)g_msg3)[n * 8 + q] = m;
    ((float4*)g_root3)[n * 8 + q] = ar;
}

// -------- gather layer3 fused with pool: pooled[batch[n]] += relu(...) --------
__global__ __launch_bounds__(256) void k_gather3(const float* __restrict__ b3,
                                                 const void* __restrict__ batch) {
    int t = blockIdx.x * 256 + threadIdx.x;
    int n = t >> 3, q = t & 7;
    if (n >= NN) return;
    int beg = g_rowptr[n], end = g_rowptr[n + 1];
    float4 acc = make_float4(0.f, 0.f, 0.f, 0.f);
    const uint2* mp = (const uint2*)g_msg3;
#pragma unroll 4
    for (int e = beg; e < end; e++) {
        int s = __ldg(&g_srcs[e]);
        uint2 v = mp[s * 8 + q];
        __half2 h0 = reinterpret_cast<__half2&>(v.x);
        __half2 h1 = reinterpret_cast<__half2&>(v.y);
        float2 f0 = __half22float2(h0), f1 = __half22float2(h1);
        acc.x += f0.x; acc.y += f0.y; acc.z += f1.x; acc.w += f1.y;
    }
    float4 r = ((const float4*)g_root3)[n * 8 + q];
    float4 h;
    h.x = fmaxf(r.x + acc.x + b3[4 * q + 0], 0.f);
    h.y = fmaxf(r.y + acc.y + b3[4 * q + 1], 0.f);
    h.z = fmaxf(r.z + acc.z + b3[4 * q + 2], 0.f);
    h.w = fmaxf(r.w + acc.w + b3[4 * q + 3], 0.f);
    int g;
    if (g_b64) g = (int)((const long long*)batch)[n];
    else       g = ((const int*)batch)[n];
    red4(g_pooled + g * 32 + q * 4, h);
}

// ---------------- out = pooled @ Wlin + blin ----------------
__global__ __launch_bounds__(64) void k_final(const float* __restrict__ Wlin,
                                              const float* __restrict__ blin,
                                              float* __restrict__ out) {
    __shared__ float sW[32 * 64];
    int tid = threadIdx.x;
    for (int i = tid; i < 2048; i += 64) sW[i] = Wlin[i];
    __syncthreads();
    int g = blockIdx.x;
    float acc = blin[tid];
    const float* p = g_pooled + g * 32;
#pragma unroll
    for (int k = 0; k < 32; k++) acc += p[k] * sW[k * 64 + tid];
    out[g * 64 + tid] = acc;
}

// ---------------- launch ----------------
extern "C" void kernel_launch(void* const* d_in, const int* in_sizes, int n_in,
                              void* d_out, int out_size) {
    const float* x     = (const float*)d_in[0];
    const void*  ei    = d_in[1];
    const void*  batch = d_in[2];
    const float* W1r = (const float*)d_in[3];
    const float* W1n = (const float*)d_in[4];
    const float* b1  = (const float*)d_in[5];
    const float* W2r = (const float*)d_in[6];
    const float* W2n = (const float*)d_in[7];
    const float* b2  = (const float*)d_in[8];
    const float* W3r = (const float*)d_in[9];
    const float* W3n = (const float*)d_in[10];
    const float* b3  = (const float*)d_in[11];
    const float* Wlin = (const float*)d_in[12];
    const float* blin = (const float*)d_in[13];
    float* out = (float*)d_out;

    const int NODE_BLKS = (NN + 255) / 256;       // 391
    const int GATH_BLKS = (NN * 8) / 256;         // 3125 exact

    k_init<<<NODE_BLKS, 256>>>((const int*)ei, (const int*)batch);
    k_hist<<<(NE / 4 + 255) / 256, 256>>>(ei);
    k_scan1<<<SCAN_NBLK, SCAN_BLK>>>();
    k_scan2<<<1, 128>>>();
    k_scan3<<<SCAN_NBLK, SCAN_BLK>>>();
    k_scatter<<<(NE / 2 + 255) / 256, 256>>>(ei);
    k_lin1<<<NODE_BLKS, 256>>>(x, W1r, W1n);
    k_g1n2<<<GATH_BLKS, 256>>>(b1, W2r, W2n);
    k_g2n3<<<GATH_BLKS, 256>>>(b2, W3r, W3n);
    k_gather3<<<GATH_BLKS, 256>>>(b3, batch);
    k_final<<<NG, 64>>>(Wlin, blin, out);
}

// round 7
// speedup vs baseline: 1.0533x; 1.0271x over previous
#include <cuda_runtime.h>
#include <cuda_fp16.h>

#define NN 100000
#define NE 3200000
#define NG 1000
#define ALLOC_BLK 1024
#define ALLOC_NBLK ((NN + ALLOC_BLK - 1) / ALLOC_BLK)   // 98

// ---------------- scratch (device globals) ----------------
__device__ __align__(16) __half g_msg1[NN * 16];
__device__ __align__(16) float  g_root1[NN * 16];
__device__ __align__(16) __half g_msg2[NN * 32];
__device__ __align__(16) float  g_root2[NN * 32];
__device__ __align__(16) __half g_msg3[NN * 32];
__device__ __align__(16) float  g_root3[NN * 32];
__device__ __align__(16) float  g_pooled[NG * 32];
__device__ int g_cnt[NN];
__device__ int g_start[NN];
__device__ int g_wptr[NN];
__device__ int g_srcs[NE];
__device__ int g_total;
__device__ int g_ei64;
__device__ int g_b64;

// ---------------- helpers ----------------
__device__ __forceinline__ void red4(float* addr, float4 v) {
    asm volatile("red.global.add.v4.f32 [%0], {%1,%2,%3,%4};"
                 :: "l"(addr), "f"(v.x), "f"(v.y), "f"(v.z), "f"(v.w) : "memory");
}
__device__ __forceinline__ unsigned pk(float a, float b) {
    __half2 h = __floats2half2_rn(a, b);
    return reinterpret_cast<unsigned&>(h);
}

// ---------------- init + detect + layer-1 matmuls, one kernel ----------------
// Zeroes cnt/pooled/total; block 0 detects int64 vs int32 (odd int32 words of
// int64 data are zero high halves); all blocks then compute
// msg1 = x@W1n (fp16) and root1 = x@W1r.
__global__ __launch_bounds__(256) void k_init_lin1(const float* __restrict__ x,
                                                   const float* __restrict__ W1r,
                                                   const float* __restrict__ W1n,
                                                   const int* __restrict__ ei,
                                                   const int* __restrict__ batch) {
    __shared__ float4 sWn[512];  // 128x16
    __shared__ float4 sWr[512];
    __shared__ int s_ei, s_b;
    int tid = threadIdx.x;
    if (tid == 0) { s_ei = 0; s_b = 0; }
    for (int i = tid; i < 512; i += 256) {
        sWn[i] = ((const float4*)W1n)[i];
        sWr[i] = ((const float4*)W1r)[i];
    }
    __syncthreads();
    if (blockIdx.x == 0) {
        if (tid < 64) {
            long long p = 1 + 2LL * tid * 49999;          // odd, < 6.4M
            if (ei[p] != 0) atomicOr(&s_ei, 1);
        } else if (tid < 96) {
            int p = (NN - 1) - 2 * (tid - 64);            // odd, near top (sorted batch)
            if (batch[p] != 0) atomicOr(&s_b, 1);
        }
        __syncthreads();   // block-0-local barrier; all 256 threads reach it
        if (tid == 0) {
            g_ei64 = (s_ei == 0);
            g_b64 = (s_b == 0);
            g_total = 0;
        }
    }
    int n = blockIdx.x * 256 + tid;
    if (n < NN) g_cnt[n] = 0;
    if (n < NG * 32) g_pooled[n] = 0.f;
    if (n >= NN) return;
    float accn[16], accr[16];
#pragma unroll
    for (int o = 0; o < 16; o++) { accn[o] = 0.f; accr[o] = 0.f; }
    const float4* xr = (const float4*)(x + (long long)n * 128);
#pragma unroll 4
    for (int k4 = 0; k4 < 32; k4++) {
        float4 xv = xr[k4];
        float xs[4] = {xv.x, xv.y, xv.z, xv.w};
#pragma unroll
        for (int kk = 0; kk < 4; kk++) {
            int k = (k4 << 2) + kk;
#pragma unroll
            for (int o4 = 0; o4 < 4; o4++) {
                float4 wn = sWn[(k << 2) + o4];
                float4 wr = sWr[(k << 2) + o4];
                accn[(o4 << 2) + 0] += xs[kk] * wn.x;
                accn[(o4 << 2) + 1] += xs[kk] * wn.y;
                accn[(o4 << 2) + 2] += xs[kk] * wn.z;
                accn[(o4 << 2) + 3] += xs[kk] * wn.w;
                accr[(o4 << 2) + 0] += xs[kk] * wr.x;
                accr[(o4 << 2) + 1] += xs[kk] * wr.y;
                accr[(o4 << 2) + 2] += xs[kk] * wr.z;
                accr[(o4 << 2) + 3] += xs[kk] * wr.w;
            }
        }
    }
    uint4 m0, m1;
    m0.x = pk(accn[0], accn[1]);   m0.y = pk(accn[2], accn[3]);
    m0.z = pk(accn[4], accn[5]);   m0.w = pk(accn[6], accn[7]);
    m1.x = pk(accn[8], accn[9]);   m1.y = pk(accn[10], accn[11]);
    m1.z = pk(accn[12], accn[13]); m1.w = pk(accn[14], accn[15]);
    uint4* mp = (uint4*)(g_msg1 + n * 16);
    mp[0] = m0; mp[1] = m1;
    float4* r = (float4*)(g_root1 + n * 16);
#pragma unroll
    for (int o4 = 0; o4 < 4; o4++)
        r[o4] = make_float4(accr[o4 * 4], accr[o4 * 4 + 1], accr[o4 * 4 + 2], accr[o4 * 4 + 3]);
}

// ---------------- histogram: 4 edges per thread ----------------
__global__ __launch_bounds__(256) void k_hist(const void* __restrict__ ei) {
    int t = blockIdx.x * 256 + threadIdx.x;
    int e = t * 4;
    if (e >= NE) return;
    if (g_ei64) {
        const longlong2* p = (const longlong2*)((const long long*)ei + NE);
        longlong2 a = p[t * 2], b = p[t * 2 + 1];
        atomicAdd(&g_cnt[(int)a.x], 1);
        atomicAdd(&g_cnt[(int)a.y], 1);
        atomicAdd(&g_cnt[(int)b.x], 1);
        atomicAdd(&g_cnt[(int)b.y], 1);
    } else {
        const int4* p = (const int4*)((const int*)ei + NE);
        int4 a = p[t];
        atomicAdd(&g_cnt[a.x], 1);
        atomicAdd(&g_cnt[a.y], 1);
        atomicAdd(&g_cnt[a.z], 1);
        atomicAdd(&g_cnt[a.w], 1);
    }
}

// ---------------- segment allocation: intra-block scan + one atomicAdd ------
// Segments [start[n], start[n]+cnt[n]) are disjoint and cover [0, NE); their
// placement is arrival-order dependent (benign: per-segment contents already
// depend on scatter atomic order, and sums are reorder-invariant within tol).
__global__ __launch_bounds__(ALLOC_BLK) void k_alloc() {
    __shared__ int warpsum[32];
    __shared__ int s_base;
    int tid = threadIdx.x;
    int i = blockIdx.x * ALLOC_BLK + tid;
    int val = (i < NN) ? g_cnt[i] : 0;
    int lane = tid & 31, wid = tid >> 5;
    int inc = val;
#pragma unroll
    for (int off = 1; off < 32; off <<= 1) {
        int v = __shfl_up_sync(0xffffffffu, inc, off);
        if (lane >= off) inc += v;
    }
    if (lane == 31) warpsum[wid] = inc;
    __syncthreads();
    if (wid == 0) {
        int ws = warpsum[lane];
#pragma unroll
        for (int off = 1; off < 32; off <<= 1) {
            int v = __shfl_up_sync(0xffffffffu, ws, off);
            if (lane >= off) ws += v;
        }
        warpsum[lane] = ws;
    }
    __syncthreads();
    int wofs = (wid == 0) ? 0 : warpsum[wid - 1];
    int excl = wofs + inc - val;
    if (tid == ALLOC_BLK - 1) s_base = atomicAdd(&g_total, wofs + inc);  // block total
    __syncthreads();
    if (i < NN) {
        int r = s_base + excl;
        g_start[i] = r;
        g_wptr[i] = r;
    }
}

// ---------------- scatter: 2 edges per thread ----------------
__global__ __launch_bounds__(256) void k_scatter(const void* __restrict__ ei) {
    int t = blockIdx.x * 256 + threadIdx.x;
    int e = t * 2;
    if (e >= NE) return;
    int s0, s1, d0, d1;
    if (g_ei64) {
        const longlong2* ps = (const longlong2*)ei;
        longlong2 sv = ps[t];
        longlong2 dv = ps[NE / 2 + t];
        s0 = (int)sv.x; s1 = (int)sv.y; d0 = (int)dv.x; d1 = (int)dv.y;
    } else {
        const int2* ps = (const int2*)ei;
        int2 sv = ps[t];
        int2 dv = ps[NE / 2 + t];
        s0 = sv.x; s1 = sv.y; d0 = dv.x; d1 = dv.y;
    }
    int p0 = atomicAdd(&g_wptr[d0], 1);
    g_srcs[p0] = s0;
    int p1 = atomicAdd(&g_wptr[d1], 1);
    g_srcs[p1] = s1;
}

// ====== FUSED gather1 + node2, 8 lanes/node ======
__global__ __launch_bounds__(256) void k_g1n2(const float* __restrict__ b1,
                                              const float* __restrict__ W2r,
                                              const float* __restrict__ W2n) {
    __shared__ float4 sWn[128];  // 16x32
    __shared__ float4 sWr[128];
    __shared__ float sb1[16];
    int tid = threadIdx.x;
    if (tid < 128) { sWn[tid] = ((const float4*)W2n)[tid]; sWr[tid] = ((const float4*)W2r)[tid]; }
    if (tid < 16) sb1[tid] = b1[tid];
    __syncthreads();
    int t = blockIdx.x * 256 + tid;
    int n = t >> 3, q = t & 7;
    int beg = g_start[n], end = beg + g_cnt[n];
    float accx = 0.f, accy = 0.f;
    const __half2* mp = (const __half2*)g_msg1;
#pragma unroll 4
    for (int e = beg; e < end; e++) {
        int s = __ldg(&g_srcs[e]);
        float2 f = __half22float2(mp[s * 8 + q]);
        accx += f.x; accy += f.y;
    }
    __syncwarp();
    float2 r = ((const float2*)g_root1)[n * 8 + q];
    float hx = fmaxf(r.x + accx + sb1[2 * q], 0.f);
    float hy = fmaxf(r.y + accy + sb1[2 * q + 1], 0.f);
    float4 am = make_float4(0.f, 0.f, 0.f, 0.f);
    float4 ar = make_float4(0.f, 0.f, 0.f, 0.f);
#pragma unroll
    for (int kk = 0; kk < 8; kk++) {
        float h0 = __shfl_sync(0xffffffffu, hx, kk, 8);
        float h1 = __shfl_sync(0xffffffffu, hy, kk, 8);
        float4 wn0 = sWn[(2 * kk) * 8 + q];
        float4 wr0 = sWr[(2 * kk) * 8 + q];
        float4 wn1 = sWn[(2 * kk + 1) * 8 + q];
        float4 wr1 = sWr[(2 * kk + 1) * 8 + q];
        am.x += h0 * wn0.x + h1 * wn1.x;  am.y += h0 * wn0.y + h1 * wn1.y;
        am.z += h0 * wn0.z + h1 * wn1.z;  am.w += h0 * wn0.w + h1 * wn1.w;
        ar.x += h0 * wr0.x + h1 * wr1.x;  ar.y += h0 * wr0.y + h1 * wr1.y;
        ar.z += h0 * wr0.z + h1 * wr1.z;  ar.w += h0 * wr0.w + h1 * wr1.w;
    }
    uint2 m;
    m.x = pk(am.x, am.y);
    m.y = pk(am.z, am.w);
    ((uint2*)g_msg2)[n * 8 + q] = m;
    ((float4*)g_root2)[n * 8 + q] = ar;
}

// ====== FUSED gather2 + node3, 8 lanes/node ======
__global__ __launch_bounds__(256) void k_g2n3(const float* __restrict__ b2,
                                              const float* __restrict__ W3r,
                                              const float* __restrict__ W3n) {
    __shared__ float4 sWn[256];  // 32x32
    __shared__ float4 sWr[256];
    __shared__ float sb2[32];
    int tid = threadIdx.x;
    if (tid < 256) { sWn[tid] = ((const float4*)W3n)[tid]; sWr[tid] = ((const float4*)W3r)[tid]; }
    if (tid < 32) sb2[tid] = b2[tid];
    __syncthreads();
    int t = blockIdx.x * 256 + tid;
    int n = t >> 3, q = t & 7;
    int beg = g_start[n], end = beg + g_cnt[n];
    float4 acc = make_float4(0.f, 0.f, 0.f, 0.f);
    const uint2* mp = (const uint2*)g_msg2;
#pragma unroll 4
    for (int e = beg; e < end; e++) {
        int s = __ldg(&g_srcs[e]);
        uint2 v = mp[s * 8 + q];
        __half2 h0 = reinterpret_cast<__half2&>(v.x);
        __half2 h1 = reinterpret_cast<__half2&>(v.y);
        float2 f0 = __half22float2(h0), f1 = __half22float2(h1);
        acc.x += f0.x; acc.y += f0.y; acc.z += f1.x; acc.w += f1.y;
    }
    __syncwarp();
    float4 r = ((const float4*)g_root2)[n * 8 + q];
    float h[4];
    h[0] = fmaxf(r.x + acc.x + sb2[4 * q + 0], 0.f);
    h[1] = fmaxf(r.y + acc.y + sb2[4 * q + 1], 0.f);
    h[2] = fmaxf(r.z + acc.z + sb2[4 * q + 2], 0.f);
    h[3] = fmaxf(r.w + acc.w + sb2[4 * q + 3], 0.f);
    float4 am = make_float4(0.f, 0.f, 0.f, 0.f);
    float4 ar = make_float4(0.f, 0.f, 0.f, 0.f);
#pragma unroll
    for (int kk = 0; kk < 8; kk++) {
#pragma unroll
        for (int c = 0; c < 4; c++) {
            float hk = __shfl_sync(0xffffffffu, h[c], kk, 8);
            int k = kk * 4 + c;
            float4 wn = sWn[k * 8 + q];
            float4 wr = sWr[k * 8 + q];
            am.x += hk * wn.x; am.y += hk * wn.y; am.z += hk * wn.z; am.w += hk * wn.w;
            ar.x += hk * wr.x; ar.y += hk * wr.y; ar.z += hk * wr.z; ar.w += hk * wr.w;
        }
    }
    uint2 m;
    m.x = pk(am.x, am.y);
    m.y = pk(am.z, am.w);
    ((uint2*)g_msg3)[n * 8 + q] = m;
    ((float4*)g_root3)[n * 8 + q] = ar;
}

// -------- gather layer3 fused with pool: pooled[batch[n]] += relu(...) --------
__global__ __launch_bounds__(256) void k_gather3(const float* __restrict__ b3,
                                                 const void* __restrict__ batch) {
    int t = blockIdx.x * 256 + threadIdx.x;
    int n = t >> 3, q = t & 7;
    if (n >= NN) return;
    int beg = g_start[n], end = beg + g_cnt[n];
    float4 acc = make_float4(0.f, 0.f, 0.f, 0.f);
    const uint2* mp = (const uint2*)g_msg3;
#pragma unroll 4
    for (int e = beg; e < end; e++) {
        int s = __ldg(&g_srcs[e]);
        uint2 v = mp[s * 8 + q];
        __half2 h0 = reinterpret_cast<__half2&>(v.x);
        __half2 h1 = reinterpret_cast<__half2&>(v.y);
        float2 f0 = __half22float2(h0), f1 = __half22float2(h1);
        acc.x += f0.x; acc.y += f0.y; acc.z += f1.x; acc.w += f1.y;
    }
    float4 r = ((const float4*)g_root3)[n * 8 + q];
    float4 h;
    h.x = fmaxf(r.x + acc.x + b3[4 * q + 0], 0.f);
    h.y = fmaxf(r.y + acc.y + b3[4 * q + 1], 0.f);
    h.z = fmaxf(r.z + acc.z + b3[4 * q + 2], 0.f);
    h.w = fmaxf(r.w + acc.w + b3[4 * q + 3], 0.f);
    int g;
    if (g_b64) g = (int)((const long long*)batch)[n];
    else       g = ((const int*)batch)[n];
    red4(g_pooled + g * 32 + q * 4, h);
}

// ---------------- out = pooled @ Wlin + blin ----------------
__global__ __launch_bounds__(64) void k_final(const float* __restrict__ Wlin,
                                              const float* __restrict__ blin,
                                              float* __restrict__ out) {
    __shared__ float sW[32 * 64];
    int tid = threadIdx.x;
    for (int i = tid; i < 2048; i += 64) sW[i] = Wlin[i];
    __syncthreads();
    int g = blockIdx.x;
    float acc = blin[tid];
    const float* p = g_pooled + g * 32;
#pragma unroll
    for (int k = 0; k < 32; k++) acc += p[k] * sW[k * 64 + tid];
    out[g * 64 + tid] = acc;
}

// ---------------- launch ----------------
extern "C" void kernel_launch(void* const* d_in, const int* in_sizes, int n_in,
                              void* d_out, int out_size) {
    const float* x     = (const float*)d_in[0];
    const void*  ei    = d_in[1];
    const void*  batch = d_in[2];
    const float* W1r = (const float*)d_in[3];
    const float* W1n = (const float*)d_in[4];
    const float* b1  = (const float*)d_in[5];
    const float* W2r = (const float*)d_in[6];
    const float* W2n = (const float*)d_in[7];
    const float* b2  = (const float*)d_in[8];
    const float* W3r = (const float*)d_in[9];
    const float* W3n = (const float*)d_in[10];
    const float* b3  = (const float*)d_in[11];
    const float* Wlin = (const float*)d_in[12];
    const float* blin = (const float*)d_in[13];
    float* out = (float*)d_out;

    const int NODE_BLKS = (NN + 255) / 256;       // 391
    const int GATH_BLKS = (NN * 8) / 256;         // 3125 exact

    k_init_lin1<<<NODE_BLKS, 256>>>(x, W1r, W1n, (const int*)ei, (const int*)batch);
    k_hist<<<(NE / 4 + 255) / 256, 256>>>(ei);
    k_alloc<<<ALLOC_NBLK, ALLOC_BLK>>>();
    k_scatter<<<(NE / 2 + 255) / 256, 256>>>(ei);
    k_g1n2<<<GATH_BLKS, 256>>>(b1, W2r, W2n);
    k_g2n3<<<GATH_BLKS, 256>>>(b2, W3r, W3n);
    k_gather3<<<GATH_BLKS, 256>>>(b3, batch);
    k_final<<<NG, 64>>>(Wlin, blin, out);
}